// round 8
// baseline (speedup 1.0000x reference)
#include <cuda_runtime.h>
#include <cstdint>

// LSTMModelClassify: B=2048, T=512, D=1, H=50, C=2, 2-layer LSTM + FC.
// R8: phase-split, gpt=1, full-batch. Warps 0-6 hold Whh0[g] in regs,
// warps 7-13 hold Whh1[g] in regs; phase A computes both recurrent GEMVs
// concurrently with ZERO weight smem traffic (h broadcast only).
// Phase B (warps 0-6) streams Wih1 from smem, accumulates into P1 in-place.

#define TPB 448
constexpr int NB    = 14;
constexpr int Hh    = 50;
constexpr int G4    = 200;
constexpr int Tt    = 512;
constexpr int BATCH = 2048;
constexpr int NC    = 2;
constexpr int HS    = 52;    // h-state / weight row stride (50 + 2 zero pad)
constexpr int PS    = 15;    // plane row stride (odd -> conflict-free)

// shared memory layout (floats)
constexpr int OFF_W1   = 0;                     // Wih1 [200][52]
constexpr int OFF_XS   = OFF_W1   + G4 * HS;    // x slice [14][512]
constexpr int OFF_BUFA = OFF_XS   + NB * Tt;    // h1 [14][52]
constexpr int OFF_BUFB = OFF_BUFA + NB * HS;    // h2 [14][52]
constexpr int OFF_P0   = OFF_BUFB + NB * HS;    // L1 preact (complete)
constexpr int OFF_P1   = OFF_P0   + G4 * PS;    // L2 preact (Whh1 part, then +Wih1)
constexpr int OFF_WFC  = OFF_P1   + G4 * PS;
constexpr int OFF_BFC  = OFF_WFC  + NC * Hh;
constexpr int SMEMF    = OFF_BFC  + NC;         // ~25.1K floats ≈ 100.5KB

__device__ __forceinline__ unsigned long long ffma2(unsigned long long a,
                                                    unsigned long long b,
                                                    unsigned long long c) {
    unsigned long long d;
    asm("fma.rn.f32x2 %0, %1, %2, %3;" : "=l"(d) : "l"(a), "l"(b), "l"(c));
    return d;
}

__device__ __forceinline__ void unpack2(unsigned long long a, float& x, float& y) {
    unsigned lo, hi;
    asm("mov.b64 {%0, %1}, %2;" : "=r"(lo), "=r"(hi) : "l"(a));
    x = __uint_as_float(lo);
    y = __uint_as_float(hi);
}

__device__ __forceinline__ float sigf(float x) {
    float e = __expf(-x);
    return __fdividef(1.0f, 1.0f + e);
}
__device__ __forceinline__ float tanh_(float x) {
    float e = __expf(2.0f * x);
    return 1.0f - __fdividef(2.0f, 1.0f + e);
}

__global__ void __launch_bounds__(TPB, 1) lstm_kernel(
    const float* __restrict__ x,
    const float* __restrict__ Wih0, const float* __restrict__ Whh0,
    const float* __restrict__ bih0, const float* __restrict__ bhh0,
    const float* __restrict__ Wih1, const float* __restrict__ Whh1,
    const float* __restrict__ bih1, const float* __restrict__ bhh1,
    const float* __restrict__ Wfc,  const float* __restrict__ bfc,
    float* __restrict__ out)
{
    extern __shared__ __align__(16) float sm[];
    const int tid = threadIdx.x;
    const int b0  = blockIdx.x * NB;

    for (int i = tid; i < SMEMF; i += TPB) sm[i] = 0.0f;   // zero: pads + h init
    __syncthreads();

    float* W1   = sm + OFF_W1;
    float* xs   = sm + OFF_XS;
    float* bufA = sm + OFF_BUFA;
    float* bufB = sm + OFF_BUFB;
    float* P0   = sm + OFF_P0;
    float* P1   = sm + OFF_P1;
    float* wfc  = sm + OFF_WFC;
    float* bfcs = sm + OFF_BFC;

    // stage Wih1 (phase-B streaming), x slice, fc
    for (int i = tid; i < G4 * Hh; i += TPB) {
        int g = i / Hh, k = i % Hh;
        W1[g * HS + k] = Wih1[i];
    }
    for (int i = tid; i < NB * Tt; i += TPB) {
        int b = i / Tt, t = i % Tt;
        int gb = b0 + b;
        xs[i] = (gb < BATCH) ? x[gb * Tt + t] : 0.0f;
    }
    for (int i = tid; i < NC * Hh; i += TPB) wfc[i] = Wfc[i];
    if (tid < NC) bfcs[tid] = bfc[tid];

    // ---- roles: warps 0-6 -> Whh0 (matsel 0); warps 7-13 -> Whh1 (matsel 1) ----
    const int warp   = tid >> 5;
    const int lane   = tid & 31;
    const int matsel = (warp >= 7) ? 1 : 0;
    const int w7     = matsel ? (warp - 7) : warp;
    const int gg     = w7 * 32 + lane;           // 0..223
    const bool gact  = gg < G4;
    const int  g     = gact ? gg : 0;            // clamp dummies

    // recurrent weights register-resident: 26 u64 (50 floats + pad)
    unsigned long long wreg[26];
    {
        const float* wsrc = matsel ? (Whh1 + g * Hh) : (Whh0 + g * Hh);
        const unsigned long long* ws = reinterpret_cast<const unsigned long long*>(wsrc);
#pragma unroll
        for (int i = 0; i < 25; ++i) wreg[i] = ws[i];
        wreg[25] = 0ULL;
    }
    float bias = 0.f, wxg = 0.f;
    if (gact) {
        if (matsel == 0) { bias = bih0[g] + bhh0[g]; wxg = Wih0[g]; }
        else             { bias = bih1[g] + bhh1[g]; }
    }
    const float* hsrcA = matsel ? bufB : bufA;   // phase-A h source
    float*       plA   = matsel ? P1   : P0;     // phase-A dest plane
    const float* wrowB = W1 + g * HS;            // phase-B weight row (smem)

    // elementwise role: 700 cells over 448 threads (<=2 each)
    float c1s[2] = {0.f, 0.f}, c2s[2] = {0.f, 0.f};

    __syncthreads();

    for (int t = 0; t < Tt; ++t) {
        // ---- Phase A: Whh0@h1(t-1) (warps 0-6)  ||  Whh1@h2(t-1) (warps 7-13)
        //      register weights, broadcast h loads, zero weight traffic ----
        {
            unsigned long long acc[NB];
#pragma unroll
            for (int b = 0; b < NB; ++b) acc[b] = 0ULL;
#pragma unroll
            for (int k4 = 0; k4 < 13; ++k4) {
#pragma unroll
                for (int b = 0; b < NB; ++b) {
                    ulonglong2 hv = *reinterpret_cast<const ulonglong2*>(hsrcA + b * HS + 4 * k4);
                    acc[b] = ffma2(hv.x, wreg[2 * k4],     acc[b]);
                    acc[b] = ffma2(hv.y, wreg[2 * k4 + 1], acc[b]);
                }
            }
            if (gact) {
#pragma unroll
                for (int b = 0; b < NB; ++b) {
                    float lo, hi;
                    unpack2(acc[b], lo, hi);
                    float extra = (matsel == 0)
                        ? fmaf(wxg, xs[b * Tt + t], bias)
                        : bias;
                    plA[g * PS + b] = lo + hi + extra;
                }
            }
        }
        __syncthreads();

        // ---- L1 elementwise: P0 (complete preact) -> bufA = h1(t) ----
#pragma unroll
        for (int r = 0; r < 2; ++r) {
            int u = tid + TPB * r;
            if (u < Hh * NB) {
                int b = u / Hh, j = u % Hh;
                float gi = P0[j * PS + b];
                float gf = P0[(j + 50) * PS + b];
                float gg2 = P0[(j + 100) * PS + b];
                float go = P0[(j + 150) * PS + b];
                float cc = sigf(gf) * c1s[r] + sigf(gi) * tanh_(gg2);
                c1s[r] = cc;
                bufA[b * HS + j] = sigf(go) * tanh_(cc);
            }
        }
        __syncthreads();

        // ---- Phase B (warps 0-6): Wih1 @ h1(t), weights streamed from smem;
        //      accumulate into P1 in-place (P1 already has Whh1@h2 + bias1) ----
        if (matsel == 0) {
            unsigned long long acc[NB];
#pragma unroll
            for (int b = 0; b < NB; ++b) acc[b] = 0ULL;
#pragma unroll
            for (int k4 = 0; k4 < 13; ++k4) {
                ulonglong2 wv = *reinterpret_cast<const ulonglong2*>(wrowB + 4 * k4);
#pragma unroll
                for (int b = 0; b < NB; ++b) {
                    ulonglong2 hv = *reinterpret_cast<const ulonglong2*>(bufA + b * HS + 4 * k4);
                    acc[b] = ffma2(hv.x, wv.x, acc[b]);
                    acc[b] = ffma2(hv.y, wv.y, acc[b]);
                }
            }
            if (gact) {
#pragma unroll
                for (int b = 0; b < NB; ++b) {
                    float lo, hi;
                    unpack2(acc[b], lo, hi);
                    P1[g * PS + b] += lo + hi;
                }
            }
        }
        __syncthreads();

        // ---- L2 elementwise: P1 (complete preact) -> bufB = h2(t) ----
#pragma unroll
        for (int r = 0; r < 2; ++r) {
            int u = tid + TPB * r;
            if (u < Hh * NB) {
                int b = u / Hh, j = u % Hh;
                float gi = P1[j * PS + b];
                float gf = P1[(j + 50) * PS + b];
                float gg2 = P1[(j + 100) * PS + b];
                float go = P1[(j + 150) * PS + b];
                float cc = sigf(gf) * c2s[r] + sigf(gi) * tanh_(gg2);
                c2s[r] = cc;
                bufB[b * HS + j] = sigf(go) * tanh_(cc);
            }
        }
        __syncthreads();
    }

    // ---- Final FC on last h2 ----
    if (tid < NB * NC) {
        int bl = tid >> 1;
        int c  = tid & 1;
        int gb = b0 + bl;
        if (gb < BATCH) {
            float s = bfcs[c];
#pragma unroll
            for (int j = 0; j < Hh; ++j) s += wfc[c * Hh + j] * bufB[bl * HS + j];
            out[gb * NC + c] = s;
        }
    }
}

extern "C" void kernel_launch(void* const* d_in, const int* in_sizes, int n_in,
                              void* d_out, int out_size) {
    const float* x    = (const float*)d_in[0];
    const float* Wih0 = (const float*)d_in[1];
    const float* Whh0 = (const float*)d_in[2];
    const float* bih0 = (const float*)d_in[3];
    const float* bhh0 = (const float*)d_in[4];
    const float* Wih1 = (const float*)d_in[5];
    const float* Whh1 = (const float*)d_in[6];
    const float* bih1 = (const float*)d_in[7];
    const float* bhh1 = (const float*)d_in[8];
    const float* Wfc  = (const float*)d_in[9];
    const float* bfc  = (const float*)d_in[10];
    float* out = (float*)d_out;

    const int smem_bytes = SMEMF * (int)sizeof(float);
    cudaFuncSetAttribute(lstm_kernel, cudaFuncAttributeMaxDynamicSharedMemorySize, smem_bytes);

    const int grid = (BATCH + NB - 1) / NB;   // 147 blocks, one wave
    lstm_kernel<<<grid, TPB, smem_bytes>>>(x, Wih0, Whh0, bih0, bhh0,
                                           Wih1, Whh1, bih1, bhh1,
                                           Wfc, bfc, out);
}